// round 4
// baseline (speedup 1.0000x reference)
#include <cuda_runtime.h>

#define Bb 8
#define Nn_ 1024
#define Dd 1024
#define Hh 16
#define HD 64
#define QSCALE 0.125f   // 64^-0.5, exact power of two

// Scratch (device globals: no allocations allowed)
__device__ float g_q[Bb * Hh * Nn_ * HD];      // [bh][n][d], pre-scaled by QSCALE
__device__ float g_k[Bb * Hh * Nn_ * HD];
__device__ float g_v[Bb * Hh * Nn_ * HD];
__device__ float g_heads[Bb * Nn_ * Dd];       // [b][n][h*HD+d]

// ---------------------------------------------------------------------------
// Generic fp32 SGEMM: C[M,N] = A[M,K] @ W[K,N] + bias[N]
// 128x128 tile, BK=8, 256 threads, 8x8 register blocking. 8KB static smem.
// MODE 0: plain row-major C output, A from parameter
// MODE 1: A from parameter, QKV scatter epilogue into g_q/g_k/g_v (q scaled)
// MODE 2: A = g_heads (bound in DEVICE code -- __device__ symbols must not be
//         passed from host!), plain row-major C output
// ---------------------------------------------------------------------------
template <int MODE>
__global__ __launch_bounds__(256)
void sgemm_kernel(const float* __restrict__ A,
                  const float* __restrict__ W,
                  const float* __restrict__ bias,
                  float* __restrict__ C,
                  int M, int N, int K)
{
    __shared__ float As[8][128];
    __shared__ float Bs[8][128];

    // Bind g_heads from device code for MODE 2.
    const float* __restrict__ Ain = (MODE == 2) ? (const float*)g_heads : A;

    const int tid = threadIdx.x;
    const int r0 = blockIdx.y * 128;
    const int c0 = blockIdx.x * 128;
    const int tx = tid & 15;        // 0..15 -> col group
    const int ty = tid >> 4;        // 0..15 -> row group

    const int a_row = tid >> 1;            // 0..127
    const int a_c4  = (tid & 1) * 4;       // 0 or 4
    const int b_row = tid >> 5;            // 0..7
    const int b_c4  = (tid & 31) * 4;      // 0..124

    const float* Aptr = Ain + (size_t)(r0 + a_row) * K + a_c4;
    const float* Wptr = W + (size_t)b_row * N + c0 + b_c4;

    float acc[8][8];
#pragma unroll
    for (int i = 0; i < 8; i++)
#pragma unroll
        for (int j = 0; j < 8; j++) acc[i][j] = 0.0f;

    for (int k0 = 0; k0 < K; k0 += 8) {
        float4 av = *(const float4*)(Aptr + k0);
        float4 bv = *(const float4*)(Wptr + (size_t)k0 * N);
        As[a_c4 + 0][a_row] = av.x;
        As[a_c4 + 1][a_row] = av.y;
        As[a_c4 + 2][a_row] = av.z;
        As[a_c4 + 3][a_row] = av.w;
        *(float4*)&Bs[b_row][b_c4] = bv;
        __syncthreads();

#pragma unroll
        for (int k = 0; k < 8; k++) {
            float ra[8], rb[8];
            *(float4*)&ra[0] = *(const float4*)&As[k][ty * 8];
            *(float4*)&ra[4] = *(const float4*)&As[k][ty * 8 + 4];
            *(float4*)&rb[0] = *(const float4*)&Bs[k][tx * 8];
            *(float4*)&rb[4] = *(const float4*)&Bs[k][tx * 8 + 4];
#pragma unroll
            for (int i = 0; i < 8; i++)
#pragma unroll
                for (int j = 0; j < 8; j++)
                    acc[i][j] = fmaf(ra[i], rb[j], acc[i][j]);
        }
        __syncthreads();
    }

    const int rowBase = r0 + ty * 8;
    const int colBase = c0 + tx * 8;

    if (MODE != 1) {
        float bvals[8];
#pragma unroll
        for (int j = 0; j < 8; j++) bvals[j] = bias[colBase + j];
#pragma unroll
        for (int i = 0; i < 8; i++) {
            float4 o0, o1;
            o0.x = acc[i][0] + bvals[0]; o0.y = acc[i][1] + bvals[1];
            o0.z = acc[i][2] + bvals[2]; o0.w = acc[i][3] + bvals[3];
            o1.x = acc[i][4] + bvals[4]; o1.y = acc[i][5] + bvals[5];
            o1.z = acc[i][6] + bvals[6]; o1.w = acc[i][7] + bvals[7];
            float* crow = C + (size_t)(rowBase + i) * N + colBase;
            *(float4*)(crow)     = o0;
            *(float4*)(crow + 4) = o1;
        }
    } else {
        // QKV scatter: col -> (h, t, d). 8-col group never crosses a 64/192
        // boundary since colBase % 8 == 0 and 8 | 64, 8 | 192.
        const int h     = colBase / 192;
        const int rem   = colBase % 192;
        const int t     = rem / 64;          // 0=q 1=k 2=v
        const int dbase = rem % 64;
        float* dst = (t == 0) ? g_q : (t == 1) ? g_k : g_v;
        const float sc = (t == 0) ? QSCALE : 1.0f;

        float bvals[8];
#pragma unroll
        for (int j = 0; j < 8; j++) bvals[j] = bias[colBase + j];

#pragma unroll
        for (int i = 0; i < 8; i++) {
            const int row = rowBase + i;       // 0..8191 = b*1024 + n
            const int b   = row >> 10;
            const int n   = row & 1023;
            const size_t off = (((size_t)(b * Hh + h) << 10) + n) * HD + dbase;
            float4 o0, o1;
            o0.x = (acc[i][0] + bvals[0]) * sc; o0.y = (acc[i][1] + bvals[1]) * sc;
            o0.z = (acc[i][2] + bvals[2]) * sc; o0.w = (acc[i][3] + bvals[3]) * sc;
            o1.x = (acc[i][4] + bvals[4]) * sc; o1.y = (acc[i][5] + bvals[5]) * sc;
            o1.z = (acc[i][6] + bvals[6]) * sc; o1.w = (acc[i][7] + bvals[7]) * sc;
            *(float4*)(dst + off)     = o0;
            *(float4*)(dst + off + 4) = o1;
        }
    }
}

// ---------------------------------------------------------------------------
// Flash-style attention: one block = (bh, 64 query rows), K/V tiles of 32.
// 256 threads. S micro-tile 4x2 per thread, O micro-tile 4x4.
// STATIC shared memory, 44,032 B total (< 48 KB: no attribute API needed).
// ---------------------------------------------------------------------------
__global__ __launch_bounds__(256)
void attn_kernel()
{
    __shared__ float Qs[64][68];   // [d][row]   17,408 B
    __shared__ float Ks[64][36];   // [d][col]    9,216 B
    __shared__ float Vs[32][68];   // [col][d]    8,704 B
    __shared__ float Ps[32][68];   // [col][row]  8,704 B

    const int tid = threadIdx.x;
    const int bh  = blockIdx.y;                 // 0..127
    const int r0  = blockIdx.x * 64;
    const int b   = bh >> 4;
    const int h   = bh & 15;

    const float* qg = g_q + (size_t)bh * Nn_ * HD;
    const float* kg = g_k + (size_t)bh * Nn_ * HD;
    const float* vg = g_v + (size_t)bh * Nn_ * HD;

    const int tx = tid & 15;   // col group
    const int ty = tid >> 4;   // row group (4 rows)

    // Load Q tile transposed: Qs[d][row]  (64 rows x 64 d)
#pragma unroll
    for (int i = 0; i < 16; i++) {
        int idx = i * 256 + tid;
        int row = idx >> 6;
        int d   = idx & 63;
        Qs[d][row] = qg[(size_t)(r0 + row) * HD + d];
    }

    float acc[4][4];
#pragma unroll
    for (int i = 0; i < 4; i++)
#pragma unroll
        for (int j = 0; j < 4; j++) acc[i][j] = 0.0f;
    float m_i[4], l_i[4];
#pragma unroll
    for (int i = 0; i < 4; i++) { m_i[i] = -3.0e38f; l_i[i] = 0.0f; }

    __syncthreads();

    for (int kt = 0; kt < Nn_ / 32; kt++) {
        const int c0 = kt * 32;
        // Load K (transposed) and V (natural): 32 rows x 64 d each
#pragma unroll
        for (int i = 0; i < 8; i++) {
            int idx = i * 256 + tid;     // 0..2047
            int row = idx >> 6;          // 0..31
            int d   = idx & 63;
            Ks[d][row] = kg[(size_t)(c0 + row) * HD + d];
            Vs[row][d] = vg[(size_t)(c0 + row) * HD + d];
        }
        __syncthreads();

        // S = Q @ K^T : 4 rows x 2 cols per thread  (q pre-scaled)
        float s[4][2];
#pragma unroll
        for (int i = 0; i < 4; i++) { s[i][0] = 0.0f; s[i][1] = 0.0f; }
#pragma unroll 8
        for (int k = 0; k < 64; k++) {
            float4 qv = *(const float4*)&Qs[k][ty * 4];
            float2 kv = *(const float2*)&Ks[k][tx * 2];
            float qa[4] = {qv.x, qv.y, qv.z, qv.w};
#pragma unroll
            for (int i = 0; i < 4; i++) {
                s[i][0] = fmaf(qa[i], kv.x, s[i][0]);
                s[i][1] = fmaf(qa[i], kv.y, s[i][1]);
            }
        }

        // Row max over this tile (16 tx lanes share each ty)
        float rmax[4];
#pragma unroll
        for (int i = 0; i < 4; i++) rmax[i] = fmaxf(s[i][0], s[i][1]);
#pragma unroll
        for (int off = 8; off >= 1; off >>= 1) {
#pragma unroll
            for (int i = 0; i < 4; i++)
                rmax[i] = fmaxf(rmax[i], __shfl_xor_sync(0xffffffffu, rmax[i], off));
        }

        float newm[4], fac[4], rsum[4];
#pragma unroll
        for (int i = 0; i < 4; i++) {
            newm[i] = fmaxf(m_i[i], rmax[i]);
            fac[i]  = __expf(m_i[i] - newm[i]);
            rsum[i] = 0.0f;
        }

        float p[4][2];
#pragma unroll
        for (int i = 0; i < 4; i++)
#pragma unroll
            for (int j = 0; j < 2; j++) {
                p[i][j] = __expf(s[i][j] - newm[i]);
                rsum[i] += p[i][j];
            }
#pragma unroll
        for (int off = 8; off >= 1; off >>= 1) {
#pragma unroll
            for (int i = 0; i < 4; i++)
                rsum[i] += __shfl_xor_sync(0xffffffffu, rsum[i], off);
        }
#pragma unroll
        for (int i = 0; i < 4; i++) {
            l_i[i] = l_i[i] * fac[i] + rsum[i];
            m_i[i] = newm[i];
#pragma unroll
            for (int j = 0; j < 4; j++) acc[i][j] *= fac[i];
        }

        // Write P transposed: Ps[col][row]
#pragma unroll
        for (int i = 0; i < 4; i++)
#pragma unroll
            for (int j = 0; j < 2; j++)
                Ps[tx * 2 + j][ty * 4 + i] = p[i][j];
        __syncthreads();

        // O += P @ V
#pragma unroll 8
        for (int c = 0; c < 32; c++) {
            float4 pv = *(const float4*)&Ps[c][ty * 4];
            float4 vv = *(const float4*)&Vs[c][tx * 4];
            float pa[4] = {pv.x, pv.y, pv.z, pv.w};
            float va[4] = {vv.x, vv.y, vv.z, vv.w};
#pragma unroll
            for (int i = 0; i < 4; i++)
#pragma unroll
                for (int j = 0; j < 4; j++)
                    acc[i][j] = fmaf(pa[i], va[j], acc[i][j]);
        }
        __syncthreads();
    }

    // Finalize: heads[b][n][h*64 + d] = acc / l
#pragma unroll
    for (int i = 0; i < 4; i++) {
        const float inv = 1.0f / l_i[i];
        const int n = r0 + ty * 4 + i;
        float4 o;
        o.x = acc[i][0] * inv; o.y = acc[i][1] * inv;
        o.z = acc[i][2] * inv; o.w = acc[i][3] * inv;
        float* dst = g_heads + ((size_t)(b * Nn_ + n) * Dd) + h * HD + tx * 4;
        *(float4*)dst = o;
    }
}

// ---------------------------------------------------------------------------
extern "C" void kernel_launch(void* const* d_in, const int* in_sizes, int n_in,
                              void* d_out, int out_size)
{
    // Resolve inputs BY SIZE (all element counts are distinct):
    //   x: 8388608   W_qkv: 3145728   b_qkv: 3072   W_o: 1048576   b_o: 1024
    const float *x = 0, *W_qkv = 0, *b_qkv = 0, *W_o = 0, *b_o = 0;
    for (int i = 0; i < n_in; i++) {
        const float* p = (const float*)d_in[i];
        switch (in_sizes[i]) {
            case 8388608: x     = p; break;
            case 3145728: W_qkv = p; break;
            case 3072:    b_qkv = p; break;
            case 1048576: W_o   = p; break;
            case 1024:    b_o   = p; break;
            default: break;
        }
    }
    float* out = (float*)d_out;                   // (8,1024,1024) fp32

    const int M = Bb * Nn_;     // 8192

    // 1) QKV projection with Q/K/V scatter epilogue (Q pre-scaled)
    {
        dim3 grid(3 * Dd / 128, M / 128);   // (24, 64)
        sgemm_kernel<1><<<grid, 256>>>(x, W_qkv, b_qkv, (float*)0, M, 3 * Dd, Dd);
    }

    // 2) Attention (flash-style, online softmax) — static smem only
    {
        dim3 grid(Nn_ / 64, Bb * Hh);       // (16, 128)
        attn_kernel<<<grid, 256>>>();
    }

    // 3) Output projection — A bound to g_heads INSIDE the kernel (MODE 2)
    {
        dim3 grid(Dd / 128, M / 128);       // (8, 64)
        sgemm_kernel<2><<<grid, 256>>>((const float*)0, W_o, b_o, out, M, Dd, Dd);
    }
}

// round 5
// speedup vs baseline: 1.5989x; 1.5989x over previous
#include <cuda_runtime.h>
#include <cstdint>

#define Bb 8
#define Nn_ 1024
#define Dd 1024
#define Hh 16
#define HD 64
#define QSCALE 0.125f   // 64^-0.5, exact power of two

// Scratch (device globals: no allocations allowed)
__device__ float g_q[Bb * Hh * Nn_ * HD];      // [bh][n][d], pre-scaled by QSCALE
__device__ float g_k[Bb * Hh * Nn_ * HD];
__device__ float g_v[Bb * Hh * Nn_ * HD];
__device__ float g_heads[Bb * Nn_ * Dd];       // [b][n][h*HD+d]

// ---------------------------------------------------------------------------
// TF32 helpers
// ---------------------------------------------------------------------------
__device__ __forceinline__ uint32_t f2tf32(float f) {
    uint32_t u;
    asm("cvt.rna.tf32.f32 %0, %1;" : "=r"(u) : "f"(f));
    return u;
}

__device__ __forceinline__ void mma_tf32(float c[4],
                                         uint32_t a0, uint32_t a1,
                                         uint32_t a2, uint32_t a3,
                                         uint32_t b0, uint32_t b1) {
    asm volatile(
        "mma.sync.aligned.m16n8k8.row.col.f32.tf32.tf32.f32 "
        "{%0,%1,%2,%3}, {%4,%5,%6,%7}, {%8,%9}, {%0,%1,%2,%3};"
        : "+f"(c[0]), "+f"(c[1]), "+f"(c[2]), "+f"(c[3])
        : "r"(a0), "r"(a1), "r"(a2), "r"(a3), "r"(b0), "r"(b1));
}

// ---------------------------------------------------------------------------
// TF32 tensor-core GEMM: C[M,N] = A[M,K] @ W[K,N] + bias[N]
// Block tile 128x128, BK=16, 256 threads = 8 warps (2 along M x 4 along N),
// warp tile 64x32 = 4x4 atoms of m16n8k8. tf32 conversion at smem-store time.
// MODE 0: plain row-major C output, A from parameter
// MODE 1: QKV scatter epilogue into g_q/g_k/g_v (q scaled by QSCALE)
// MODE 2: A = g_heads (bound in DEVICE code), plain row-major C output
// ---------------------------------------------------------------------------
template <int MODE>
__global__ __launch_bounds__(256)
void sgemm_kernel(const float* __restrict__ A,
                  const float* __restrict__ W,
                  const float* __restrict__ bias,
                  float* __restrict__ C,
                  int M, int N, int K)
{
    __shared__ uint32_t As[128][20];   // [row][k], pad 16->20: frag loads conflict-free
    __shared__ uint32_t Bs[16][136];   // [k][col], pad 128->136: frag loads conflict-free

    const float* __restrict__ Ain = (MODE == 2) ? (const float*)g_heads : A;

    const int tid  = threadIdx.x;
    const int lane = tid & 31;
    const int warp = tid >> 5;
    const int warpM = warp & 1;        // 0..1
    const int warpN = warp >> 1;       // 0..3

    const int r0 = blockIdx.y * 128;
    const int c0 = blockIdx.x * 128;

    // Global-load mapping
    const int a_row = tid >> 1;             // 0..127 (2 threads per row)
    const int a_kc  = (tid & 1) * 8;        // 0 or 8 (two float4 each)
    const int b_kr  = tid >> 5;             // 0..7  (i adds 8)
    const int b_c4  = (tid & 31) * 4;       // 0..124

    const float* Aptr = Ain + (size_t)(r0 + a_row) * K + a_kc;
    const float* Wptr = W + (size_t)b_kr * N + c0 + b_c4;

    float acc[4][4][4];                     // [am][bn][reg]
#pragma unroll
    for (int i = 0; i < 4; i++)
#pragma unroll
        for (int j = 0; j < 4; j++)
#pragma unroll
            for (int r = 0; r < 4; r++) acc[i][j][r] = 0.0f;

    const int lr = lane >> 2;   // 0..7
    const int lc = lane & 3;    // 0..3

    for (int k0 = 0; k0 < K; k0 += 16) {
        // ---- load A tile: 128 rows x 16 k ----
        {
            float4 v0 = *(const float4*)(Aptr + k0);
            float4 v1 = *(const float4*)(Aptr + k0 + 4);
            As[a_row][a_kc + 0] = f2tf32(v0.x);
            As[a_row][a_kc + 1] = f2tf32(v0.y);
            As[a_row][a_kc + 2] = f2tf32(v0.z);
            As[a_row][a_kc + 3] = f2tf32(v0.w);
            As[a_row][a_kc + 4] = f2tf32(v1.x);
            As[a_row][a_kc + 5] = f2tf32(v1.y);
            As[a_row][a_kc + 6] = f2tf32(v1.z);
            As[a_row][a_kc + 7] = f2tf32(v1.w);
        }
        // ---- load B tile: 16 k x 128 cols ----
#pragma unroll
        for (int i = 0; i < 2; i++) {
            int kr = b_kr + i * 8;
            float4 v = *(const float4*)(Wptr + (size_t)(k0 + i * 8 - b_kr + kr) * 0 +
                                        (size_t)(k0 + kr) * N);
            // (expression kept simple:)
            v = *(const float4*)(W + (size_t)(k0 + kr) * N + c0 + b_c4);
            Bs[kr][b_c4 + 0] = f2tf32(v.x);
            Bs[kr][b_c4 + 1] = f2tf32(v.y);
            Bs[kr][b_c4 + 2] = f2tf32(v.z);
            Bs[kr][b_c4 + 3] = f2tf32(v.w);
        }
        __syncthreads();

#pragma unroll
        for (int kk = 0; kk < 16; kk += 8) {
            // A fragments: 4 m-atoms
            uint32_t af[4][4];
#pragma unroll
            for (int am = 0; am < 4; am++) {
                const int row = warpM * 64 + am * 16 + lr;
                af[am][0] = As[row][kk + lc];
                af[am][1] = As[row + 8][kk + lc];
                af[am][2] = As[row][kk + lc + 4];
                af[am][3] = As[row + 8][kk + lc + 4];
            }
            // B fragments: 4 n-atoms
            uint32_t bf[4][2];
#pragma unroll
            for (int bn = 0; bn < 4; bn++) {
                const int col = warpN * 32 + bn * 8 + lr;
                bf[bn][0] = Bs[kk + lc][col];
                bf[bn][1] = Bs[kk + lc + 4][col];
            }
#pragma unroll
            for (int am = 0; am < 4; am++)
#pragma unroll
                for (int bn = 0; bn < 4; bn++)
                    mma_tf32(acc[am][bn], af[am][0], af[am][1], af[am][2], af[am][3],
                             bf[bn][0], bf[bn][1]);
        }
        __syncthreads();
    }

    // ---- epilogue ----
#pragma unroll
    for (int am = 0; am < 4; am++) {
        const int row0 = r0 + warpM * 64 + am * 16 + lr;
        const int row1 = row0 + 8;
#pragma unroll
        for (int bn = 0; bn < 4; bn++) {
            const int atomcol = c0 + warpN * 32 + bn * 8;   // multiple of 8
            const int colp = atomcol + lc * 2;
            const float b0v = bias[colp];
            const float b1v = bias[colp + 1];

            if (MODE != 1) {
                float2 o0 = make_float2(acc[am][bn][0] + b0v, acc[am][bn][1] + b1v);
                float2 o1 = make_float2(acc[am][bn][2] + b0v, acc[am][bn][3] + b1v);
                *(float2*)(C + (size_t)row0 * N + colp) = o0;
                *(float2*)(C + (size_t)row1 * N + colp) = o1;
            } else {
                // col -> (h, t, d): 8-col atom never crosses a 64/192 boundary
                const int h     = atomcol / 192;
                const int rem   = atomcol % 192;
                const int t     = rem / 64;          // 0=q 1=k 2=v
                const int dbase = (rem % 64) + lc * 2;
                float* dst = (t == 0) ? g_q : (t == 1) ? g_k : g_v;
                const float sc = (t == 0) ? QSCALE : 1.0f;

                const int b0r = row0 >> 10, n0 = row0 & 1023;
                const int b1r = row1 >> 10, n1 = row1 & 1023;
                const size_t off0 = (((size_t)(b0r * Hh + h) << 10) + n0) * HD + dbase;
                const size_t off1 = (((size_t)(b1r * Hh + h) << 10) + n1) * HD + dbase;
                float2 o0 = make_float2((acc[am][bn][0] + b0v) * sc,
                                        (acc[am][bn][1] + b1v) * sc);
                float2 o1 = make_float2((acc[am][bn][2] + b0v) * sc,
                                        (acc[am][bn][3] + b1v) * sc);
                *(float2*)(dst + off0) = o0;
                *(float2*)(dst + off1) = o1;
            }
        }
    }
}

// ---------------------------------------------------------------------------
// Flash-style attention (unchanged from R4 — known good).
// One block = (bh, 64 query rows), K/V tiles of 32. 256 threads.
// ---------------------------------------------------------------------------
__global__ __launch_bounds__(256)
void attn_kernel()
{
    __shared__ float Qs[64][68];   // [d][row]
    __shared__ float Ks[64][36];   // [d][col]
    __shared__ float Vs[32][68];   // [col][d]
    __shared__ float Ps[32][68];   // [col][row]

    const int tid = threadIdx.x;
    const int bh  = blockIdx.y;
    const int r0  = blockIdx.x * 64;
    const int b   = bh >> 4;
    const int h   = bh & 15;

    const float* qg = g_q + (size_t)bh * Nn_ * HD;
    const float* kg = g_k + (size_t)bh * Nn_ * HD;
    const float* vg = g_v + (size_t)bh * Nn_ * HD;

    const int tx = tid & 15;
    const int ty = tid >> 4;

#pragma unroll
    for (int i = 0; i < 16; i++) {
        int idx = i * 256 + tid;
        int row = idx >> 6;
        int d   = idx & 63;
        Qs[d][row] = qg[(size_t)(r0 + row) * HD + d];
    }

    float acc[4][4];
#pragma unroll
    for (int i = 0; i < 4; i++)
#pragma unroll
        for (int j = 0; j < 4; j++) acc[i][j] = 0.0f;
    float m_i[4], l_i[4];
#pragma unroll
    for (int i = 0; i < 4; i++) { m_i[i] = -3.0e38f; l_i[i] = 0.0f; }

    __syncthreads();

    for (int kt = 0; kt < Nn_ / 32; kt++) {
        const int c0 = kt * 32;
#pragma unroll
        for (int i = 0; i < 8; i++) {
            int idx = i * 256 + tid;
            int row = idx >> 6;
            int d   = idx & 63;
            Ks[d][row] = kg[(size_t)(c0 + row) * HD + d];
            Vs[row][d] = vg[(size_t)(c0 + row) * HD + d];
        }
        __syncthreads();

        float s[4][2];
#pragma unroll
        for (int i = 0; i < 4; i++) { s[i][0] = 0.0f; s[i][1] = 0.0f; }
#pragma unroll 8
        for (int k = 0; k < 64; k++) {
            float4 qv = *(const float4*)&Qs[k][ty * 4];
            float2 kv = *(const float2*)&Ks[k][tx * 2];
            float qa[4] = {qv.x, qv.y, qv.z, qv.w};
#pragma unroll
            for (int i = 0; i < 4; i++) {
                s[i][0] = fmaf(qa[i], kv.x, s[i][0]);
                s[i][1] = fmaf(qa[i], kv.y, s[i][1]);
            }
        }

        float rmax[4];
#pragma unroll
        for (int i = 0; i < 4; i++) rmax[i] = fmaxf(s[i][0], s[i][1]);
#pragma unroll
        for (int off = 8; off >= 1; off >>= 1) {
#pragma unroll
            for (int i = 0; i < 4; i++)
                rmax[i] = fmaxf(rmax[i], __shfl_xor_sync(0xffffffffu, rmax[i], off));
        }

        float newm[4], fac[4], rsum[4];
#pragma unroll
        for (int i = 0; i < 4; i++) {
            newm[i] = fmaxf(m_i[i], rmax[i]);
            fac[i]  = __expf(m_i[i] - newm[i]);
            rsum[i] = 0.0f;
        }

        float p[4][2];
#pragma unroll
        for (int i = 0; i < 4; i++)
#pragma unroll
            for (int j = 0; j < 2; j++) {
                p[i][j] = __expf(s[i][j] - newm[i]);
                rsum[i] += p[i][j];
            }
#pragma unroll
        for (int off = 8; off >= 1; off >>= 1) {
#pragma unroll
            for (int i = 0; i < 4; i++)
                rsum[i] += __shfl_xor_sync(0xffffffffu, rsum[i], off);
        }
#pragma unroll
        for (int i = 0; i < 4; i++) {
            l_i[i] = l_i[i] * fac[i] + rsum[i];
            m_i[i] = newm[i];
#pragma unroll
            for (int j = 0; j < 4; j++) acc[i][j] *= fac[i];
        }

#pragma unroll
        for (int i = 0; i < 4; i++)
#pragma unroll
            for (int j = 0; j < 2; j++)
                Ps[tx * 2 + j][ty * 4 + i] = p[i][j];
        __syncthreads();

#pragma unroll 8
        for (int c = 0; c < 32; c++) {
            float4 pv = *(const float4*)&Ps[c][ty * 4];
            float4 vv = *(const float4*)&Vs[c][tx * 4];
            float pa[4] = {pv.x, pv.y, pv.z, pv.w};
            float va[4] = {vv.x, vv.y, vv.z, vv.w};
#pragma unroll
            for (int i = 0; i < 4; i++)
#pragma unroll
                for (int j = 0; j < 4; j++)
                    acc[i][j] = fmaf(pa[i], va[j], acc[i][j]);
        }
        __syncthreads();
    }

#pragma unroll
    for (int i = 0; i < 4; i++) {
        const float inv = 1.0f / l_i[i];
        const int n = r0 + ty * 4 + i;
        float4 o;
        o.x = acc[i][0] * inv; o.y = acc[i][1] * inv;
        o.z = acc[i][2] * inv; o.w = acc[i][3] * inv;
        float* dst = g_heads + ((size_t)(b * Nn_ + n) * Dd) + h * HD + tx * 4;
        *(float4*)dst = o;
    }
}

// ---------------------------------------------------------------------------
extern "C" void kernel_launch(void* const* d_in, const int* in_sizes, int n_in,
                              void* d_out, int out_size)
{
    // Resolve inputs BY SIZE (all element counts are distinct):
    const float *x = 0, *W_qkv = 0, *b_qkv = 0, *W_o = 0, *b_o = 0;
    for (int i = 0; i < n_in; i++) {
        const float* p = (const float*)d_in[i];
        switch (in_sizes[i]) {
            case 8388608: x     = p; break;
            case 3145728: W_qkv = p; break;
            case 3072:    b_qkv = p; break;
            case 1048576: W_o   = p; break;
            case 1024:    b_o   = p; break;
            default: break;
        }
    }
    float* out = (float*)d_out;

    const int M = Bb * Nn_;     // 8192

    // 1) QKV projection (tf32 tensor cores) with Q/K/V scatter epilogue
    {
        dim3 grid(3 * Dd / 128, M / 128);   // (24, 64)
        sgemm_kernel<1><<<grid, 256>>>(x, W_qkv, b_qkv, (float*)0, M, 3 * Dd, Dd);
    }

    // 2) Attention (flash-style, online softmax)
    {
        dim3 grid(Nn_ / 64, Bb * Hh);       // (16, 128)
        attn_kernel<<<grid, 256>>>();
    }

    // 3) Output projection (tf32), A bound to g_heads in device code
    {
        dim3 grid(Dd / 128, M / 128);       // (8, 64)
        sgemm_kernel<2><<<grid, 256>>>((const float*)0, W_o, b_o, out, M, Dd, Dd);
    }
}

// round 6
// speedup vs baseline: 2.1745x; 1.3600x over previous
#include <cuda_runtime.h>
#include <cstdint>

#define Bb 8
#define Nn_ 1024
#define Dd 1024
#define Hh 16
#define HD 64
#define QSCALE 0.125f   // 64^-0.5, exact power of two

// Scratch (device globals: no allocations allowed)
__device__ float g_q[Bb * Hh * Nn_ * HD];      // [bh][n][d], pre-scaled by QSCALE
__device__ float g_k[Bb * Hh * Nn_ * HD];
__device__ float g_v[Bb * Hh * Nn_ * HD];
__device__ float g_heads[Bb * Nn_ * Dd];       // [b][n][h*HD+d]

// ---------------------------------------------------------------------------
// TF32 helpers
// ---------------------------------------------------------------------------
__device__ __forceinline__ uint32_t f2tf32(float f) {
    uint32_t u;
    asm("cvt.rna.tf32.f32 %0, %1;" : "=r"(u) : "f"(f));
    return u;
}

__device__ __forceinline__ void mma_tf32(float c[4],
                                         uint32_t a0, uint32_t a1,
                                         uint32_t a2, uint32_t a3,
                                         uint32_t b0, uint32_t b1) {
    asm volatile(
        "mma.sync.aligned.m16n8k8.row.col.f32.tf32.tf32.f32 "
        "{%0,%1,%2,%3}, {%4,%5,%6,%7}, {%8,%9}, {%0,%1,%2,%3};"
        : "+f"(c[0]), "+f"(c[1]), "+f"(c[2]), "+f"(c[3])
        : "r"(a0), "r"(a1), "r"(a2), "r"(a3), "r"(b0), "r"(b1));
}

// ---------------------------------------------------------------------------
// TF32 tensor-core GEMM: C[M,N] = A[M,K] @ W[K,N] + bias[N]
// Block tile 128x128, BK=16, 256 threads = 8 warps (2 M x 4 N),
// warp tile 64x32 = 4x4 atoms of m16n8k8. tf32 conversion at smem-store time.
// MODE 0: plain output; MODE 1: QKV scatter; MODE 2: A = g_heads (device bind)
// ---------------------------------------------------------------------------
template <int MODE>
__global__ __launch_bounds__(256)
void sgemm_kernel(const float* __restrict__ A,
                  const float* __restrict__ W,
                  const float* __restrict__ bias,
                  float* __restrict__ C,
                  int M, int N, int K)
{
    __shared__ uint32_t As[128][20];
    __shared__ uint32_t Bs[16][136];

    const float* __restrict__ Ain = (MODE == 2) ? (const float*)g_heads : A;

    const int tid  = threadIdx.x;
    const int lane = tid & 31;
    const int warp = tid >> 5;
    const int warpM = warp & 1;
    const int warpN = warp >> 1;

    const int r0 = blockIdx.y * 128;
    const int c0 = blockIdx.x * 128;

    const int a_row = tid >> 1;
    const int a_kc  = (tid & 1) * 8;
    const int b_kr  = tid >> 5;
    const int b_c4  = (tid & 31) * 4;

    const float* Aptr = Ain + (size_t)(r0 + a_row) * K + a_kc;

    float acc[4][4][4];
#pragma unroll
    for (int i = 0; i < 4; i++)
#pragma unroll
        for (int j = 0; j < 4; j++)
#pragma unroll
            for (int r = 0; r < 4; r++) acc[i][j][r] = 0.0f;

    const int lr = lane >> 2;
    const int lc = lane & 3;

    for (int k0 = 0; k0 < K; k0 += 16) {
        {
            float4 v0 = *(const float4*)(Aptr + k0);
            float4 v1 = *(const float4*)(Aptr + k0 + 4);
            As[a_row][a_kc + 0] = f2tf32(v0.x);
            As[a_row][a_kc + 1] = f2tf32(v0.y);
            As[a_row][a_kc + 2] = f2tf32(v0.z);
            As[a_row][a_kc + 3] = f2tf32(v0.w);
            As[a_row][a_kc + 4] = f2tf32(v1.x);
            As[a_row][a_kc + 5] = f2tf32(v1.y);
            As[a_row][a_kc + 6] = f2tf32(v1.z);
            As[a_row][a_kc + 7] = f2tf32(v1.w);
        }
#pragma unroll
        for (int i = 0; i < 2; i++) {
            int kr = b_kr + i * 8;
            float4 v = *(const float4*)(W + (size_t)(k0 + kr) * N + c0 + b_c4);
            Bs[kr][b_c4 + 0] = f2tf32(v.x);
            Bs[kr][b_c4 + 1] = f2tf32(v.y);
            Bs[kr][b_c4 + 2] = f2tf32(v.z);
            Bs[kr][b_c4 + 3] = f2tf32(v.w);
        }
        __syncthreads();

#pragma unroll
        for (int kk = 0; kk < 16; kk += 8) {
            uint32_t af[4][4];
#pragma unroll
            for (int am = 0; am < 4; am++) {
                const int row = warpM * 64 + am * 16 + lr;
                af[am][0] = As[row][kk + lc];
                af[am][1] = As[row + 8][kk + lc];
                af[am][2] = As[row][kk + lc + 4];
                af[am][3] = As[row + 8][kk + lc + 4];
            }
            uint32_t bf[4][2];
#pragma unroll
            for (int bn = 0; bn < 4; bn++) {
                const int col = warpN * 32 + bn * 8 + lr;
                bf[bn][0] = Bs[kk + lc][col];
                bf[bn][1] = Bs[kk + lc + 4][col];
            }
#pragma unroll
            for (int am = 0; am < 4; am++)
#pragma unroll
                for (int bn = 0; bn < 4; bn++)
                    mma_tf32(acc[am][bn], af[am][0], af[am][1], af[am][2], af[am][3],
                             bf[bn][0], bf[bn][1]);
        }
        __syncthreads();
    }

#pragma unroll
    for (int am = 0; am < 4; am++) {
        const int row0 = r0 + warpM * 64 + am * 16 + lr;
        const int row1 = row0 + 8;
#pragma unroll
        for (int bn = 0; bn < 4; bn++) {
            const int atomcol = c0 + warpN * 32 + bn * 8;
            const int colp = atomcol + lc * 2;
            const float b0v = bias[colp];
            const float b1v = bias[colp + 1];

            if (MODE != 1) {
                float2 o0 = make_float2(acc[am][bn][0] + b0v, acc[am][bn][1] + b1v);
                float2 o1 = make_float2(acc[am][bn][2] + b0v, acc[am][bn][3] + b1v);
                *(float2*)(C + (size_t)row0 * N + colp) = o0;
                *(float2*)(C + (size_t)row1 * N + colp) = o1;
            } else {
                const int h     = atomcol / 192;
                const int rem   = atomcol % 192;
                const int t     = rem / 64;
                const int dbase = (rem % 64) + lc * 2;
                float* dst = (t == 0) ? g_q : (t == 1) ? g_k : g_v;
                const float sc = (t == 0) ? QSCALE : 1.0f;

                const int b0r = row0 >> 10, n0 = row0 & 1023;
                const int b1r = row1 >> 10, n1 = row1 & 1023;
                const size_t off0 = (((size_t)(b0r * Hh + h) << 10) + n0) * HD + dbase;
                const size_t off1 = (((size_t)(b1r * Hh + h) << 10) + n1) * HD + dbase;
                float2 o0 = make_float2((acc[am][bn][0] + b0v) * sc,
                                        (acc[am][bn][1] + b1v) * sc);
                float2 o1 = make_float2((acc[am][bn][2] + b0v) * sc,
                                        (acc[am][bn][3] + b1v) * sc);
                *(float2*)(dst + off0) = o0;
                *(float2*)(dst + off1) = o1;
            }
        }
    }
}

// ---------------------------------------------------------------------------
// Tensor-core flash attention (tf32 mma, split K and split V for accuracy).
// Block = (bh, 64 q-rows). 128 threads = 4 warps; warp w owns rows 16w..16w+15.
// K/V tiles of 32. Dynamic smem, exactly 65,536 B:
//   Qs  [64][68]  tf32 Q (natural [row][d]) -- A-frag loads conflict-free
//   Khi [64][40]  tf32 hi(K) transposed [d][seq] -- B-frag loads conflict-free
//   Klo [64][40]  tf32 lo(K)
//   Vhi [32][72]  tf32 hi(V) natural [seq][d] -- B-frag loads conflict-free
//   Vlo [32][72]  tf32 lo(V)
//   Ps  [64][36]  tf32 P [row][seq] -- per-warp private rows; A-frag conflict-free
// S = Q@(Khi+Klo)^T  (2-term);  O += P@(Vhi+Vlo)  (2-term).
// ---------------------------------------------------------------------------
#define ATTN_SMEM_BYTES 65536

__global__ __launch_bounds__(128)
void attn_mma_kernel()
{
    extern __shared__ uint32_t sm[];
    uint32_t* Qs  = sm;                       // 64*68 = 4352
    uint32_t* Khi = sm + 4352;                // 64*40 = 2560
    uint32_t* Klo = Khi + 2560;
    uint32_t* Vhi = Klo + 2560;               // 32*72 = 2304
    uint32_t* Vlo = Vhi + 2304;
    uint32_t* Ps  = Vlo + 2304;               // 64*36 = 2304

    const int tid  = threadIdx.x;
    const int lane = tid & 31;
    const int warp = tid >> 5;                // 0..3
    const int lr   = lane >> 2;               // 0..7
    const int lc   = lane & 3;                // 0..3

    const int bh = blockIdx.y;                // 0..127
    const int r0 = blockIdx.x * 64;
    const int b  = bh >> 4;
    const int h  = bh & 15;

    const float* qg = g_q + (size_t)bh * Nn_ * HD;
    const float* kg = g_k + (size_t)bh * Nn_ * HD;
    const float* vg = g_v + (size_t)bh * Nn_ * HD;

    // ---- load Q tile (64x64), tf32, natural layout ----
#pragma unroll
    for (int i = 0; i < 32; i++) {
        int idx = i * 128 + tid;
        int row = idx >> 6;
        int d   = idx & 63;
        Qs[row * 68 + d] = f2tf32(qg[(size_t)(r0 + row) * HD + d]);
    }

    float oacc[8][4];
#pragma unroll
    for (int bn = 0; bn < 8; bn++)
#pragma unroll
        for (int r = 0; r < 4; r++) oacc[bn][r] = 0.0f;
    float m0 = -3.0e38f, m1 = -3.0e38f, l0 = 0.0f, l1 = 0.0f;

    const int wrow = warp * 16;               // warp's row base within tile

    __syncthreads();

    for (int kt = 0; kt < Nn_ / 32; kt++) {
        const int c0 = kt * 32;

        // ---- load K tile transposed + split (conflict-free stores) ----
        // 512 float4 loads: idx4 -> row = idx4&31, dgrp = idx4>>5 (d0 = 4*dgrp)
#pragma unroll
        for (int i = 0; i < 4; i++) {
            int idx4 = i * 128 + tid;
            int row  = idx4 & 31;
            int d0   = (idx4 >> 5) * 4;
            float4 kv = *(const float4*)(kg + (size_t)(c0 + row) * HD + d0);
            float kf[4] = {kv.x, kv.y, kv.z, kv.w};
#pragma unroll
            for (int j = 0; j < 4; j++) {
                uint32_t hi = f2tf32(kf[j]);
                Khi[(d0 + j) * 40 + row] = hi;
                Klo[(d0 + j) * 40 + row] = f2tf32(kf[j] - __uint_as_float(hi));
            }
        }
        // ---- load V tile natural + split ----
#pragma unroll
        for (int i = 0; i < 4; i++) {
            int idx4 = i * 128 + tid;
            int row  = idx4 >> 4;              // 0..31
            int d0   = (idx4 & 15) * 4;
            float4 vv = *(const float4*)(vg + (size_t)(c0 + row) * HD + d0);
            float vf[4] = {vv.x, vv.y, vv.z, vv.w};
            uint32_t hiw[4], low[4];
#pragma unroll
            for (int j = 0; j < 4; j++) {
                hiw[j] = f2tf32(vf[j]);
                low[j] = f2tf32(vf[j] - __uint_as_float(hiw[j]));
            }
            *(uint4*)&Vhi[row * 72 + d0] = make_uint4(hiw[0], hiw[1], hiw[2], hiw[3]);
            *(uint4*)&Vlo[row * 72 + d0] = make_uint4(low[0], low[1], low[2], low[3]);
        }
        __syncthreads();

        // ---- S = Q @ K^T (2-term split on K) ----
        float sacc[4][4];
#pragma unroll
        for (int bn = 0; bn < 4; bn++)
#pragma unroll
            for (int r = 0; r < 4; r++) sacc[bn][r] = 0.0f;

#pragma unroll
        for (int kk = 0; kk < 64; kk += 8) {
            uint32_t a0 = Qs[(wrow + lr) * 68 + kk + lc];
            uint32_t a1 = Qs[(wrow + 8 + lr) * 68 + kk + lc];
            uint32_t a2 = Qs[(wrow + lr) * 68 + kk + lc + 4];
            uint32_t a3 = Qs[(wrow + 8 + lr) * 68 + kk + lc + 4];
#pragma unroll
            for (int bn = 0; bn < 4; bn++) {
                const int col = bn * 8 + lr;
                uint32_t bh0 = Khi[(kk + lc) * 40 + col];
                uint32_t bh1 = Khi[(kk + lc + 4) * 40 + col];
                uint32_t bl0 = Klo[(kk + lc) * 40 + col];
                uint32_t bl1 = Klo[(kk + lc + 4) * 40 + col];
                mma_tf32(sacc[bn], a0, a1, a2, a3, bh0, bh1);
                mma_tf32(sacc[bn], a0, a1, a2, a3, bl0, bl1);
            }
        }

        // ---- online softmax (rows lr and lr+8; quad = lanes sharing lr) ----
        float rmax0 = -3.0e38f, rmax1 = -3.0e38f;
#pragma unroll
        for (int bn = 0; bn < 4; bn++) {
            rmax0 = fmaxf(rmax0, fmaxf(sacc[bn][0], sacc[bn][1]));
            rmax1 = fmaxf(rmax1, fmaxf(sacc[bn][2], sacc[bn][3]));
        }
        rmax0 = fmaxf(rmax0, __shfl_xor_sync(0xffffffffu, rmax0, 1));
        rmax0 = fmaxf(rmax0, __shfl_xor_sync(0xffffffffu, rmax0, 2));
        rmax1 = fmaxf(rmax1, __shfl_xor_sync(0xffffffffu, rmax1, 1));
        rmax1 = fmaxf(rmax1, __shfl_xor_sync(0xffffffffu, rmax1, 2));

        const float newm0 = fmaxf(m0, rmax0);
        const float newm1 = fmaxf(m1, rmax1);
        const float fac0  = __expf(m0 - newm0);
        const float fac1  = __expf(m1 - newm1);

        float p[4][4];
        float rsum0 = 0.0f, rsum1 = 0.0f;
#pragma unroll
        for (int bn = 0; bn < 4; bn++) {
            p[bn][0] = __expf(sacc[bn][0] - newm0);
            p[bn][1] = __expf(sacc[bn][1] - newm0);
            p[bn][2] = __expf(sacc[bn][2] - newm1);
            p[bn][3] = __expf(sacc[bn][3] - newm1);
            rsum0 += p[bn][0] + p[bn][1];
            rsum1 += p[bn][2] + p[bn][3];
        }
        rsum0 += __shfl_xor_sync(0xffffffffu, rsum0, 1);
        rsum0 += __shfl_xor_sync(0xffffffffu, rsum0, 2);
        rsum1 += __shfl_xor_sync(0xffffffffu, rsum1, 1);
        rsum1 += __shfl_xor_sync(0xffffffffu, rsum1, 2);

        l0 = l0 * fac0 + rsum0;  m0 = newm0;
        l1 = l1 * fac1 + rsum1;  m1 = newm1;
#pragma unroll
        for (int bn = 0; bn < 8; bn++) {
            oacc[bn][0] *= fac0; oacc[bn][1] *= fac0;
            oacc[bn][2] *= fac1; oacc[bn][3] *= fac1;
        }

        // ---- store P (tf32) to per-warp-private rows of Ps ----
#pragma unroll
        for (int bn = 0; bn < 4; bn++) {
            Ps[(wrow + lr) * 36 + bn * 8 + 2 * lc]         = f2tf32(p[bn][0]);
            Ps[(wrow + lr) * 36 + bn * 8 + 2 * lc + 1]     = f2tf32(p[bn][1]);
            Ps[(wrow + 8 + lr) * 36 + bn * 8 + 2 * lc]     = f2tf32(p[bn][2]);
            Ps[(wrow + 8 + lr) * 36 + bn * 8 + 2 * lc + 1] = f2tf32(p[bn][3]);
        }
        __syncwarp();

        // ---- O += P @ V (2-term split on V) ----
#pragma unroll
        for (int kk = 0; kk < 32; kk += 8) {
            uint32_t a0 = Ps[(wrow + lr) * 36 + kk + lc];
            uint32_t a1 = Ps[(wrow + 8 + lr) * 36 + kk + lc];
            uint32_t a2 = Ps[(wrow + lr) * 36 + kk + lc + 4];
            uint32_t a3 = Ps[(wrow + 8 + lr) * 36 + kk + lc + 4];
#pragma unroll
            for (int bn = 0; bn < 8; bn++) {
                const int col = bn * 8 + lr;
                uint32_t bh0 = Vhi[(kk + lc) * 72 + col];
                uint32_t bh1 = Vhi[(kk + lc + 4) * 72 + col];
                uint32_t bl0 = Vlo[(kk + lc) * 72 + col];
                uint32_t bl1 = Vlo[(kk + lc + 4) * 72 + col];
                mma_tf32(oacc[bn], a0, a1, a2, a3, bh0, bh1);
                mma_tf32(oacc[bn], a0, a1, a2, a3, bl0, bl1);
            }
        }
        __syncthreads();   // protect K/V/Ps smem before next tile's stores
    }

    // ---- finalize: heads[b][n][h*64+d] = O / l ----
    const float inv0 = 1.0f / l0;
    const float inv1 = 1.0f / l1;
    const int row0 = r0 + wrow + lr;
    const int row1 = row0 + 8;
#pragma unroll
    for (int bn = 0; bn < 8; bn++) {
        const int col = h * HD + bn * 8 + 2 * lc;
        *(float2*)(g_heads + ((size_t)(b * Nn_ + row0) * Dd) + col) =
            make_float2(oacc[bn][0] * inv0, oacc[bn][1] * inv0);
        *(float2*)(g_heads + ((size_t)(b * Nn_ + row1) * Dd) + col) =
            make_float2(oacc[bn][2] * inv1, oacc[bn][3] * inv1);
    }
}

// ---------------------------------------------------------------------------
extern "C" void kernel_launch(void* const* d_in, const int* in_sizes, int n_in,
                              void* d_out, int out_size)
{
    // Resolve inputs BY SIZE (all element counts are distinct):
    const float *x = 0, *W_qkv = 0, *b_qkv = 0, *W_o = 0, *b_o = 0;
    for (int i = 0; i < n_in; i++) {
        const float* p = (const float*)d_in[i];
        switch (in_sizes[i]) {
            case 8388608: x     = p; break;
            case 3145728: W_qkv = p; break;
            case 3072:    b_qkv = p; break;
            case 1048576: W_o   = p; break;
            case 1024:    b_o   = p; break;
            default: break;
        }
    }
    float* out = (float*)d_out;

    const int M = Bb * Nn_;     // 8192

    // Idempotent, capture-safe: allow 64KB dynamic smem for attention
    cudaFuncSetAttribute(attn_mma_kernel,
                         cudaFuncAttributeMaxDynamicSharedMemorySize,
                         ATTN_SMEM_BYTES);

    // 1) QKV projection (tf32 tensor cores) with Q/K/V scatter epilogue
    {
        dim3 grid(3 * Dd / 128, M / 128);   // (24, 64)
        sgemm_kernel<1><<<grid, 256>>>(x, W_qkv, b_qkv, (float*)0, M, 3 * Dd, Dd);
    }

    // 2) Attention (flash-style, tf32 tensor cores, split-K/V accuracy)
    {
        dim3 grid(Nn_ / 64, Bb * Hh);       // (16, 128)
        attn_mma_kernel<<<grid, 128, ATTN_SMEM_BYTES>>>();
    }

    // 3) Output projection (tf32), A bound to g_heads in device code
    {
        dim3 grid(Dd / 128, M / 128);       // (8, 64)
        sgemm_kernel<2><<<grid, 256>>>((const float*)0, W_o, b_o, out, M, Dd, Dd);
    }
}